// round 11
// baseline (speedup 1.0000x reference)
#include <cuda_runtime.h>
#include <cuda_fp16.h>
#include <cstdint>

// ---------------------------------------------------------------------------
// out[8192,4096] = x[8192,4096] @ dequantNF4(qweight,scales)[4096,4096] + bias
// sm_100 PTX target => no tcgen05. mma.sync.m16n8k16 f16 fallback path.
// R9: occupancy experiment. 128x128 CTA tile, warp tile 64x32, 2 CTAs/SM
// (launch_bounds(256,2), 97KB smem, 3-stage cp.async pipeline) so one CTA's
// MMA issue covers the other CTA's fill/sync convoys.
// ---------------------------------------------------------------------------
#define MDIM 8192
#define NDIM 4096
#define KDIM 4096
#define KWROWS (KDIM / 8)

#define BM 128
#define BN 128
#define BK 64                          // fp16 elems / K-chunk: 128-byte rows
#define STAGES 3
#define NITER (KDIM / BK)              // 64
#define A_BYTES (BM * BK * 2)          // 16384
#define B_BYTES (BN * BK * 2)          // 16384
#define STAGE_BYTES (A_BYTES + B_BYTES)            // 32768
#define SMEM_TOTAL (1024 + STAGES * STAGE_BYTES)   // 99328 (x2 CTAs = 198656)

// SW128 swizzle for 128-byte rows
#define SWZ(bo) ((bo) ^ (((bo) >> 3) & 0x70))

__device__ __align__(16) __half g_X[(size_t)MDIM * KDIM];   // [M,K]
__device__ __align__(16) __half g_W[(size_t)NDIM * KDIM];   // [N,K] K-major

__device__ const float NF4_TBL[16] = {
    -1.0f, -0.6961928009986877f, -0.5250730514526367f, -0.39491748809814453f,
    -0.28444138169288635f, -0.18477343022823334f, -0.09105003625154495f, 0.0f,
    0.07958029955625534f, 0.16093020141124725f, 0.24611230194568634f,
    0.33791524171829224f, 0.44070982933044434f, 0.5626170039176941f,
    0.7229568362236023f, 1.0f};

__device__ __forceinline__ uint32_t smem_u32(const void* p) {
    uint32_t a;
    asm("{ .reg .u64 t; cvta.to.shared.u64 t, %1; cvt.u32.u64 %0, t; }"
        : "=r"(a) : "l"(p));
    return a;
}

#define CP_ASYNC16(smem, gptr) \
    asm volatile("cp.async.cg.shared.global [%0], [%1], 16;" \
                 :: "r"(smem), "l"(gptr) : "memory")

#define LDSM4(r, addr)                                                         \
    asm volatile("ldmatrix.sync.aligned.m8n8.x4.shared.b16 {%0,%1,%2,%3}, [%4];" \
                 : "=r"((r)[0]), "=r"((r)[1]), "=r"((r)[2]), "=r"((r)[3])      \
                 : "r"(addr))

#define MMA16816(c, a, b0, b1)                                                 \
    asm volatile("mma.sync.aligned.m16n8k16.row.col.f32.f16.f16.f32 "          \
                 "{%0,%1,%2,%3}, {%4,%5,%6,%7}, {%8,%9}, {%0,%1,%2,%3};"       \
                 : "+f"((c)[0]), "+f"((c)[1]), "+f"((c)[2]), "+f"((c)[3])      \
                 : "r"((a)[0]), "r"((a)[1]), "r"((a)[2]), "r"((a)[3]),         \
                   "r"(b0), "r"(b1))

// ---------------------------------------------------------------------------
__global__ void __launch_bounds__(256) round_x_kernel(const float4* __restrict__ x) {
    int i = blockIdx.x * 256 + threadIdx.x;
    float4 a = x[2 * i];
    float4 b = x[2 * i + 1];
    __half2 h[4];
    h[0] = __floats2half2_rn(a.x, a.y);
    h[1] = __floats2half2_rn(a.z, a.w);
    h[2] = __floats2half2_rn(b.x, b.y);
    h[3] = __floats2half2_rn(b.z, b.w);
    reinterpret_cast<float4*>(g_X)[i] = *reinterpret_cast<float4*>(h);
}

__global__ void __launch_bounds__(256) dequant_kernel(const int* __restrict__ qw,
                                                      const float* __restrict__ sc) {
    int gid = blockIdx.x * 256 + threadIdx.x;
    int kw = gid >> 12;
    int n  = gid & (NDIM - 1);
    uint32_t q = (uint32_t)qw[(size_t)kw * NDIM + n];
    float s = sc[(size_t)(kw >> 4) * NDIM + n];
    __half2 h[4];
#pragma unroll
    for (int j = 0; j < 4; ++j) {
        float lo = NF4_TBL[(q >> (8 * j)) & 15] * s;
        float hi = NF4_TBL[(q >> (8 * j + 4)) & 15] * s;
        h[j] = __floats2half2_rn(lo, hi);
    }
    *reinterpret_cast<float4*>(g_W + (size_t)n * KDIM + kw * 8) =
        *reinterpret_cast<float4*>(h);
}

// ---------------------------------------------------------------------------
// GEMM: 128x128 CTA tile, 8 warps (2x4), warp tile 64x32, occupancy 2.
// ---------------------------------------------------------------------------
struct Frag { uint32_t a[4][4]; uint32_t b[2][4]; };

__device__ __forceinline__ void load_frags(Frag& f, uint32_t stb, int ks,
                                           int a_row_base, uint32_t a_kh,
                                           int b_row_base, uint32_t b_kh) {
#pragma unroll
    for (int mt = 0; mt < 4; ++mt) {
        uint32_t bo = (uint32_t)((a_row_base + mt * 16) * 128 + ks * 32) + a_kh;
        LDSM4(f.a[mt], stb + SWZ(bo));
    }
#pragma unroll
    for (int nt = 0; nt < 2; ++nt) {
        uint32_t bo = (uint32_t)((b_row_base + nt * 16) * 128 + ks * 32) + b_kh;
        LDSM4(f.b[nt], stb + (uint32_t)A_BYTES + SWZ(bo));
    }
}

__device__ __forceinline__ void mma_step(float acc[4][4][4], const Frag& f) {
#pragma unroll
    for (int mt = 0; mt < 4; ++mt)
#pragma unroll
        for (int j = 0; j < 4; ++j)
            MMA16816(acc[mt][j], f.a[mt], f.b[j >> 1][(j & 1) * 2],
                     f.b[j >> 1][(j & 1) * 2 + 1]);
}

__global__ void __launch_bounds__(256, 2) gemm_f16(const float* __restrict__ bias,
                                                   float* __restrict__ out) {
    extern __shared__ char smem_raw[];
    const uint32_t sb = (smem_u32(smem_raw) + 1023) & ~1023u;
    const int tid  = threadIdx.x;
    const int wid  = tid >> 5;
    const int lane = tid & 31;
    const int tile_n = blockIdx.x;
    const int tile_m = blockIdx.y;
    const int wm = wid >> 2;                 // 0..1 -> m offset wm*64
    const int wn = wid & 3;                  // 0..3 -> n offset wn*32

    // per-thread cp.async offsets: A 4 chunks, B 4 chunks of 16B
    uint32_t a_sw[4], b_sw[4];
    int a_go[4], b_go[4];
#pragma unroll
    for (int j = 0; j < 4; ++j) {
        int c = tid + j * 256;               // 1024 chunks each for A and B
        int r = c >> 3, ci = c & 7;          // 8 chunks per 128B row
        uint32_t bo = (uint32_t)(r * 128 + ci * 16);
        a_sw[j] = SWZ(bo);
        a_go[j] = r * KDIM + ci * 8;
        b_sw[j] = (uint32_t)A_BYTES + SWZ(bo);
        b_go[j] = a_go[j];
    }
    const __half* Ab = g_X + (size_t)tile_m * BM * KDIM;
    const __half* Bb = g_W + (size_t)tile_n * BN * KDIM;

    // prologue: fill STAGES-1 stages
#pragma unroll
    for (int s = 0; s < STAGES - 1; ++s) {
        uint32_t stb = sb + s * STAGE_BYTES;
        const __half* ap = Ab + s * BK;
        const __half* bp = Bb + s * BK;
#pragma unroll
        for (int j = 0; j < 4; ++j) CP_ASYNC16(stb + a_sw[j], ap + a_go[j]);
#pragma unroll
        for (int j = 0; j < 4; ++j) CP_ASYNC16(stb + b_sw[j], bp + b_go[j]);
        asm volatile("cp.async.commit_group;" ::: "memory");
    }

    float acc[4][4][4];
#pragma unroll
    for (int i = 0; i < 4; ++i)
#pragma unroll
        for (int j = 0; j < 4; ++j)
#pragma unroll
            for (int k = 0; k < 4; ++k) acc[i][j][k] = 0.0f;

    const int a_row_base = wm * 64 + (lane & 15);
    const uint32_t a_kh  = (uint32_t)((lane >> 4) << 4);
    const int b_row_base = wn * 32 + ((lane >> 4) << 3) + (lane & 7);
    const uint32_t b_kh  = (uint32_t)(((lane >> 3) & 1) << 4);

    Frag f;
    int stage = 0;

#pragma unroll 1
    for (int it = 0; it < NITER; ++it) {
        asm volatile("cp.async.wait_group %0;" :: "n"(STAGES - 2) : "memory");
        __syncthreads();

        const uint32_t stb = sb + stage * STAGE_BYTES;

        load_frags(f, stb, 0, a_row_base, a_kh, b_row_base, b_kh);

        // next-stage cp.async while first LDSM batch is in flight
        int nx = it + STAGES - 1;
        if (nx < NITER) {
            int pst = stage + (STAGES - 1);
            if (pst >= STAGES) pst -= STAGES;
            uint32_t pstb = sb + pst * STAGE_BYTES;
            const __half* ap = Ab + nx * BK;
            const __half* bp = Bb + nx * BK;
#pragma unroll
            for (int j = 0; j < 4; ++j) CP_ASYNC16(pstb + a_sw[j], ap + a_go[j]);
#pragma unroll
            for (int j = 0; j < 4; ++j) CP_ASYNC16(pstb + b_sw[j], bp + b_go[j]);
        }
        asm volatile("cp.async.commit_group;" ::: "memory");

        mma_step(acc, f);                                           // ks=0
        load_frags(f, stb, 1, a_row_base, a_kh, b_row_base, b_kh);
        mma_step(acc, f);                                           // ks=1
        load_frags(f, stb, 2, a_row_base, a_kh, b_row_base, b_kh);
        mma_step(acc, f);                                           // ks=2
        load_frags(f, stb, 3, a_row_base, a_kh, b_row_base, b_kh);
        mma_step(acc, f);                                           // ks=3

        if (++stage == STAGES) stage = 0;
    }

    // epilogue: bias + store
    const int m0 = tile_m * BM + wm * 64 + (lane >> 2);
    const int n0 = tile_n * BN + wn * 32 + 2 * (lane & 3);
#pragma unroll
    for (int j = 0; j < 4; ++j) {
        const int n = n0 + j * 8;
        const float2 bv = *reinterpret_cast<const float2*>(bias + n);
#pragma unroll
        for (int mt = 0; mt < 4; ++mt) {
            const int m = m0 + mt * 16;
            float2 v0, v1;
            v0.x = acc[mt][j][0] + bv.x;
            v0.y = acc[mt][j][1] + bv.y;
            v1.x = acc[mt][j][2] + bv.x;
            v1.y = acc[mt][j][3] + bv.y;
            *reinterpret_cast<float2*>(out + (size_t)m * NDIM + n) = v0;
            *reinterpret_cast<float2*>(out + (size_t)(m + 8) * NDIM + n) = v1;
        }
    }
}

// ---------------------------------------------------------------------------
extern "C" void kernel_launch(void* const* d_in, const int* in_sizes, int n_in,
                              void* d_out, int out_size) {
    const float* x       = (const float*)d_in[0];
    const float* scales  = (const float*)d_in[1];
    const float* bias    = (const float*)d_in[2];
    const int*   qweight = (const int*)d_in[3];
    float* out = (float*)d_out;

    cudaFuncSetAttribute(gemm_f16, cudaFuncAttributeMaxDynamicSharedMemorySize,
                         SMEM_TOTAL);

    round_x_kernel<<<(MDIM * KDIM / 8) / 256, 256>>>((const float4*)x);
    dequant_kernel<<<(KWROWS * NDIM) / 256, 256>>>(qweight, scales);
    gemm_f16<<<dim3(NDIM / BN, MDIM / BM), 256, SMEM_TOTAL>>>(bias, out);
}

// round 12
// speedup vs baseline: 1.1339x; 1.1339x over previous
#include <cuda_runtime.h>
#include <cuda_fp16.h>
#include <cstdint>

// ---------------------------------------------------------------------------
// out[8192,4096] = x[8192,4096] @ dequantNF4(qweight,scales)[4096,4096] + bias
// sm_100 PTX target => no tcgen05. mma.sync.m16n8k16 f16 fallback path.
// R12: replace wait_group/__syncthreads convoy with an mbarrier ring
// (full[s] via cp.async.mbarrier.arrive, empty[s] per-warp) so warps
// decouple and crossbar(LDSM) overlaps tensor(MMA) across warps.
// ---------------------------------------------------------------------------
#define MDIM 8192
#define NDIM 4096
#define KDIM 4096
#define KWROWS (KDIM / 8)

#define BM 128
#define BN 256
#define BK 64                          // fp16 elems / K-chunk: 128-byte rows
#define STAGES 4
#define NITER (KDIM / BK)              // 64
#define A_BYTES (BM * BK * 2)          // 16384
#define B_BYTES (BN * BK * 2)          // 32768
#define STAGE_BYTES (A_BYTES + B_BYTES)            // 49152
// [align pad 1024][mbarrier zone 1024][4 stages]
#define SMEM_TOTAL (1024 + 1024 + STAGES * STAGE_BYTES)   // 198656

// SW128 swizzle for 128-byte rows
#define SWZ(bo) ((bo) ^ (((bo) >> 3) & 0x70))

__device__ __align__(16) __half g_X[(size_t)MDIM * KDIM];   // [M,K]
__device__ __align__(16) __half g_W[(size_t)NDIM * KDIM];   // [N,K] K-major

__device__ const float NF4_TBL[16] = {
    -1.0f, -0.6961928009986877f, -0.5250730514526367f, -0.39491748809814453f,
    -0.28444138169288635f, -0.18477343022823334f, -0.09105003625154495f, 0.0f,
    0.07958029955625534f, 0.16093020141124725f, 0.24611230194568634f,
    0.33791524171829224f, 0.44070982933044434f, 0.5626170039176941f,
    0.7229568362236023f, 1.0f};

__device__ __forceinline__ uint32_t smem_u32(const void* p) {
    uint32_t a;
    asm("{ .reg .u64 t; cvta.to.shared.u64 t, %1; cvt.u32.u64 %0, t; }"
        : "=r"(a) : "l"(p));
    return a;
}

#define CP_ASYNC16(smem, gptr) \
    asm volatile("cp.async.cg.shared.global [%0], [%1], 16;" \
                 :: "r"(smem), "l"(gptr) : "memory")

#define CP_ASYNC_MBAR_ARRIVE(mbar) \
    asm volatile("cp.async.mbarrier.arrive.noinc.shared.b64 [%0];" \
                 :: "r"(mbar) : "memory")

#define MBAR_INIT(addr, cnt) \
    asm volatile("mbarrier.init.shared.b64 [%0], %1;" :: "r"(addr), "r"((uint32_t)(cnt)) : "memory")

#define MBAR_ARRIVE(addr) \
    asm volatile("mbarrier.arrive.shared.b64 _, [%0];" :: "r"(addr) : "memory")

#define MBAR_WAIT(addr, par) do {                                              \
    uint32_t _m = (addr); uint32_t _p = (par); uint32_t _d;                    \
    asm volatile(                                                              \
        "{\n\t.reg .pred p;\n\t"                                               \
        "mbarrier.try_wait.parity.shared.b64 p, [%1], %2;\n\t"                 \
        "selp.b32 %0, 1, 0, p;\n\t}"                                           \
        : "=r"(_d) : "r"(_m), "r"(_p) : "memory");                             \
    if (!_d) {                                                                 \
        asm volatile(                                                          \
            "{\n\t.reg .pred P1;\n\t"                                          \
            "WL_%=:\n\t"                                                       \
            "mbarrier.try_wait.parity.shared.b64 P1, [%0], %1;\n\t"            \
            "@P1 bra.uni WD_%=;\n\t"                                           \
            "bra.uni WL_%=;\n\t"                                               \
            "WD_%=:\n\t}"                                                      \
            :: "r"(_m), "r"(_p) : "memory");                                   \
    }                                                                          \
} while (0)

#define LDSM4(r, addr)                                                         \
    asm volatile("ldmatrix.sync.aligned.m8n8.x4.shared.b16 {%0,%1,%2,%3}, [%4];" \
                 : "=r"((r)[0]), "=r"((r)[1]), "=r"((r)[2]), "=r"((r)[3])      \
                 : "r"(addr))

#define MMA16816(c, a, b0, b1)                                                 \
    asm volatile("mma.sync.aligned.m16n8k16.row.col.f32.f16.f16.f32 "          \
                 "{%0,%1,%2,%3}, {%4,%5,%6,%7}, {%8,%9}, {%0,%1,%2,%3};"       \
                 : "+f"((c)[0]), "+f"((c)[1]), "+f"((c)[2]), "+f"((c)[3])      \
                 : "r"((a)[0]), "r"((a)[1]), "r"((a)[2]), "r"((a)[3]),         \
                   "r"(b0), "r"(b1))

// ---------------------------------------------------------------------------
// Fused prelude: x->fp16 and NF4 dequant in one launch (both DRAM-bound).
// ---------------------------------------------------------------------------
#define NB_X ((MDIM * KDIM / 8) / 256)        // 16384 blocks
#define NB_W ((KWROWS * NDIM) / 256)          // 2048 blocks

__global__ void __launch_bounds__(256) prep_kernel(const float4* __restrict__ x,
                                                   const int* __restrict__ qw,
                                                   const float* __restrict__ sc) {
    if (blockIdx.x < NB_X) {
        int i = blockIdx.x * 256 + threadIdx.x;
        float4 a = x[2 * i];
        float4 b = x[2 * i + 1];
        __half2 h[4];
        h[0] = __floats2half2_rn(a.x, a.y);
        h[1] = __floats2half2_rn(a.z, a.w);
        h[2] = __floats2half2_rn(b.x, b.y);
        h[3] = __floats2half2_rn(b.z, b.w);
        reinterpret_cast<float4*>(g_X)[i] = *reinterpret_cast<float4*>(h);
    } else {
        int gid = (blockIdx.x - NB_X) * 256 + threadIdx.x;
        int kw = gid >> 12;
        int n  = gid & (NDIM - 1);
        uint32_t q = (uint32_t)qw[(size_t)kw * NDIM + n];
        float s = sc[(size_t)(kw >> 4) * NDIM + n];
        __half2 h[4];
#pragma unroll
        for (int j = 0; j < 4; ++j) {
            float lo = NF4_TBL[(q >> (8 * j)) & 15] * s;
            float hi = NF4_TBL[(q >> (8 * j + 4)) & 15] * s;
            h[j] = __floats2half2_rn(lo, hi);
        }
        *reinterpret_cast<float4*>(g_W + (size_t)n * KDIM + kw * 8) =
            *reinterpret_cast<float4*>(h);
    }
}

// ---------------------------------------------------------------------------
// GEMM: 128x256 CTA tile, 8 warps (2x4), warp tile 64x64, mbarrier ring.
// ---------------------------------------------------------------------------
struct Frag { uint32_t a[4][4]; uint32_t b[4][4]; };

__device__ __forceinline__ void load_frags(Frag& f, uint32_t stb, int ks,
                                           int a_row_base, uint32_t a_kh,
                                           int b_row_base, uint32_t b_kh) {
#pragma unroll
    for (int mt = 0; mt < 4; ++mt) {
        uint32_t bo = (uint32_t)((a_row_base + mt * 16) * 128 + ks * 32) + a_kh;
        LDSM4(f.a[mt], stb + SWZ(bo));
    }
#pragma unroll
    for (int nt = 0; nt < 4; ++nt) {
        uint32_t bo = (uint32_t)((b_row_base + nt * 16) * 128 + ks * 32) + b_kh;
        LDSM4(f.b[nt], stb + (uint32_t)A_BYTES + SWZ(bo));
    }
}

__device__ __forceinline__ void mma_step(float acc[4][8][4], const Frag& f) {
#pragma unroll
    for (int mt = 0; mt < 4; ++mt)
#pragma unroll
        for (int j = 0; j < 8; ++j)
            MMA16816(acc[mt][j], f.a[mt], f.b[j >> 1][(j & 1) * 2],
                     f.b[j >> 1][(j & 1) * 2 + 1]);
}

__global__ void __launch_bounds__(256, 1) gemm_f16(const float* __restrict__ bias,
                                                   float* __restrict__ out) {
    extern __shared__ char smem_raw[];
    const uint32_t sb = (smem_u32(smem_raw) + 1023) & ~1023u;  // mbarrier zone
    const uint32_t tb = sb + 1024;                              // tiles
    const int tid  = threadIdx.x;
    const int wid  = tid >> 5;
    const int lane = tid & 31;
    const int tile_n = blockIdx.x;
    const int tile_m = blockIdx.y;
    const int wm = wid >> 2;
    const int wn = wid & 3;

    if (tid == 0) {
#pragma unroll
        for (int s = 0; s < STAGES; ++s) {
            MBAR_INIT(sb + s * 16, 256);      // full[s]: all threads' cp.async
            MBAR_INIT(sb + s * 16 + 8, 8);    // empty[s]: one arrive per warp
        }
    }
    __syncthreads();

    // per-thread cp.async offsets (A: 4 chunks, B: 8 chunks of 16B)
    uint32_t a_sw[4], b_sw[8];
    int a_go[4], b_go[8];
#pragma unroll
    for (int j = 0; j < 4; ++j) {
        int c = tid + j * 256;
        int r = c >> 3, ci = c & 7;
        uint32_t bo = (uint32_t)(r * 128 + ci * 16);
        a_sw[j] = SWZ(bo);
        a_go[j] = r * KDIM + ci * 8;
    }
#pragma unroll
    for (int j = 0; j < 8; ++j) {
        int c = tid + j * 256;
        int r = c >> 3, ci = c & 7;
        uint32_t bo = (uint32_t)(r * 128 + ci * 16);
        b_sw[j] = (uint32_t)A_BYTES + SWZ(bo);
        b_go[j] = r * KDIM + ci * 8;
    }
    const __half* Ab = g_X + (size_t)tile_m * BM * KDIM;
    const __half* Bb = g_W + (size_t)tile_n * BN * KDIM;

    // prologue: fill ALL 4 stages (mainloop fills it+4)
#pragma unroll
    for (int s = 0; s < STAGES; ++s) {
        uint32_t stb = tb + s * STAGE_BYTES;
        const __half* ap = Ab + s * BK;
        const __half* bp = Bb + s * BK;
#pragma unroll
        for (int j = 0; j < 4; ++j) CP_ASYNC16(stb + a_sw[j], ap + a_go[j]);
#pragma unroll
        for (int j = 0; j < 8; ++j) CP_ASYNC16(stb + b_sw[j], bp + b_go[j]);
        CP_ASYNC_MBAR_ARRIVE(sb + s * 16);
    }

    float acc[4][8][4];
#pragma unroll
    for (int i = 0; i < 4; ++i)
#pragma unroll
        for (int j = 0; j < 8; ++j)
#pragma unroll
            for (int k = 0; k < 4; ++k) acc[i][j][k] = 0.0f;

    const int a_row_base = wm * 64 + (lane & 15);
    const uint32_t a_kh  = (uint32_t)((lane >> 4) << 4);
    const int b_row_base = wn * 64 + ((lane >> 4) << 3) + (lane & 7);
    const uint32_t b_kh  = (uint32_t)(((lane >> 3) & 1) << 4);

    Frag f0, f1;

#pragma unroll 1
    for (int it = 0; it < NITER; ++it) {
        const int slot = it & (STAGES - 1);
        const uint32_t ph = (uint32_t)((it >> 2) & 1);
        const uint32_t full_mb  = sb + slot * 16;
        const uint32_t empty_mb = full_mb + 8;

        MBAR_WAIT(full_mb, ph);              // data for iter it resident

        const uint32_t stb = tb + slot * STAGE_BYTES;
        load_frags(f0, stb, 0, a_row_base, a_kh, b_row_base, b_kh);
        load_frags(f1, stb, 1, a_row_base, a_kh, b_row_base, b_kh);

        mma_step(acc, f0);                                          // ks=0
        load_frags(f0, stb, 2, a_row_base, a_kh, b_row_base, b_kh); // ks=2
        mma_step(acc, f1);                                          // ks=1
        load_frags(f1, stb, 3, a_row_base, a_kh, b_row_base, b_kh); // ks=3

        // this warp is done reading slot
        if (lane == 0) MBAR_ARRIVE(empty_mb);

        mma_step(acc, f0);                                          // ks=2

        const int nx = it + STAGES;          // refill same slot, 4 ahead
        if (nx < NITER) {
            MBAR_WAIT(empty_mb, ph);         // all warps done reading iter it
            const __half* ap = Ab + nx * BK;
            const __half* bp = Bb + nx * BK;
#pragma unroll
            for (int j = 0; j < 4; ++j) CP_ASYNC16(stb + a_sw[j], ap + a_go[j]);
#pragma unroll
            for (int j = 0; j < 8; ++j) CP_ASYNC16(stb + b_sw[j], bp + b_go[j]);
            CP_ASYNC_MBAR_ARRIVE(full_mb);
        }

        mma_step(acc, f1);                                          // ks=3
    }

    // epilogue: bias + store
    const int m0 = tile_m * BM + wm * 64 + (lane >> 2);
    const int n0 = tile_n * BN + wn * 64 + 2 * (lane & 3);
#pragma unroll
    for (int j = 0; j < 8; ++j) {
        const int n = n0 + j * 8;
        const float2 bv = *reinterpret_cast<const float2*>(bias + n);
#pragma unroll
        for (int mt = 0; mt < 4; ++mt) {
            const int m = m0 + mt * 16;
            float2 v0, v1;
            v0.x = acc[mt][j][0] + bv.x;
            v0.y = acc[mt][j][1] + bv.y;
            v1.x = acc[mt][j][2] + bv.x;
            v1.y = acc[mt][j][3] + bv.y;
            *reinterpret_cast<float2*>(out + (size_t)m * NDIM + n) = v0;
            *reinterpret_cast<float2*>(out + (size_t)(m + 8) * NDIM + n) = v1;
        }
    }
}

// ---------------------------------------------------------------------------
extern "C" void kernel_launch(void* const* d_in, const int* in_sizes, int n_in,
                              void* d_out, int out_size) {
    const float* x       = (const float*)d_in[0];
    const float* scales  = (const float*)d_in[1];
    const float* bias    = (const float*)d_in[2];
    const int*   qweight = (const int*)d_in[3];
    float* out = (float*)d_out;

    cudaFuncSetAttribute(gemm_f16, cudaFuncAttributeMaxDynamicSharedMemorySize,
                         SMEM_TOTAL);

    prep_kernel<<<NB_X + NB_W, 256>>>((const float4*)x, qweight, scales);
    gemm_f16<<<dim3(NDIM / BN, MDIM / BM), 256, SMEM_TOTAL>>>(bias, out);
}

// round 13
// speedup vs baseline: 1.2100x; 1.0671x over previous
#include <cuda_runtime.h>
#include <cuda_fp16.h>
#include <cstdint>

// ---------------------------------------------------------------------------
// out[8192,4096] = x[8192,4096] @ dequantNF4(qweight,scales)[4096,4096] + bias
// sm_100 PTX target => no tcgen05. mma.sync.m16n8k16 f16 (rt~8cyc/SMSP).
// R13: cross-iteration software pipelining on the R12 mbarrier ring —
// hoist full-wait + ks0 LDSM of iter it+1 before the last mma of iter it,
// push slot refill to the iteration tail. Goal: tensor 81.5% -> ~92%.
// ---------------------------------------------------------------------------
#define MDIM 8192
#define NDIM 4096
#define KDIM 4096
#define KWROWS (KDIM / 8)

#define BM 128
#define BN 256
#define BK 64                          // fp16 elems / K-chunk: 128-byte rows
#define STAGES 4
#define NITER (KDIM / BK)              // 64
#define A_BYTES (BM * BK * 2)          // 16384
#define B_BYTES (BN * BK * 2)          // 32768
#define STAGE_BYTES (A_BYTES + B_BYTES)            // 49152
#define SMEM_TOTAL (1024 + 1024 + STAGES * STAGE_BYTES)   // 198656

#define SWZ(bo) ((bo) ^ (((bo) >> 3) & 0x70))

__device__ __align__(16) __half g_X[(size_t)MDIM * KDIM];   // [M,K]
__device__ __align__(16) __half g_W[(size_t)NDIM * KDIM];   // [N,K] K-major

__device__ const float NF4_TBL[16] = {
    -1.0f, -0.6961928009986877f, -0.5250730514526367f, -0.39491748809814453f,
    -0.28444138169288635f, -0.18477343022823334f, -0.09105003625154495f, 0.0f,
    0.07958029955625534f, 0.16093020141124725f, 0.24611230194568634f,
    0.33791524171829224f, 0.44070982933044434f, 0.5626170039176941f,
    0.7229568362236023f, 1.0f};

__device__ __forceinline__ uint32_t smem_u32(const void* p) {
    uint32_t a;
    asm("{ .reg .u64 t; cvta.to.shared.u64 t, %1; cvt.u32.u64 %0, t; }"
        : "=r"(a) : "l"(p));
    return a;
}

#define CP_ASYNC16(smem, gptr) \
    asm volatile("cp.async.cg.shared.global [%0], [%1], 16;" \
                 :: "r"(smem), "l"(gptr) : "memory")

#define CP_ASYNC_MBAR_ARRIVE(mbar) \
    asm volatile("cp.async.mbarrier.arrive.noinc.shared.b64 [%0];" \
                 :: "r"(mbar) : "memory")

#define MBAR_INIT(addr, cnt) \
    asm volatile("mbarrier.init.shared.b64 [%0], %1;" :: "r"(addr), "r"((uint32_t)(cnt)) : "memory")

#define MBAR_ARRIVE(addr) \
    asm volatile("mbarrier.arrive.shared.b64 _, [%0];" :: "r"(addr) : "memory")

#define MBAR_WAIT(addr, par) do {                                              \
    uint32_t _m = (addr); uint32_t _p = (par); uint32_t _d;                    \
    asm volatile(                                                              \
        "{\n\t.reg .pred p;\n\t"                                               \
        "mbarrier.try_wait.parity.shared.b64 p, [%1], %2;\n\t"                 \
        "selp.b32 %0, 1, 0, p;\n\t}"                                           \
        : "=r"(_d) : "r"(_m), "r"(_p) : "memory");                             \
    if (!_d) {                                                                 \
        asm volatile(                                                          \
            "{\n\t.reg .pred P1;\n\t"                                          \
            "WL_%=:\n\t"                                                       \
            "mbarrier.try_wait.parity.shared.b64 P1, [%0], %1;\n\t"            \
            "@P1 bra.uni WD_%=;\n\t"                                           \
            "bra.uni WL_%=;\n\t"                                               \
            "WD_%=:\n\t}"                                                      \
            :: "r"(_m), "r"(_p) : "memory");                                   \
    }                                                                          \
} while (0)

#define LDSM4(r, addr)                                                         \
    asm volatile("ldmatrix.sync.aligned.m8n8.x4.shared.b16 {%0,%1,%2,%3}, [%4];" \
                 : "=r"((r)[0]), "=r"((r)[1]), "=r"((r)[2]), "=r"((r)[3])      \
                 : "r"(addr))

#define MMA16816(c, a, b0, b1)                                                 \
    asm volatile("mma.sync.aligned.m16n8k16.row.col.f32.f16.f16.f32 "          \
                 "{%0,%1,%2,%3}, {%4,%5,%6,%7}, {%8,%9}, {%0,%1,%2,%3};"       \
                 : "+f"((c)[0]), "+f"((c)[1]), "+f"((c)[2]), "+f"((c)[3])      \
                 : "r"((a)[0]), "r"((a)[1]), "r"((a)[2]), "r"((a)[3]),         \
                   "r"(b0), "r"(b1))

// ---------------------------------------------------------------------------
// Fused prelude
// ---------------------------------------------------------------------------
#define NB_X ((MDIM * KDIM / 8) / 256)        // 16384 blocks
#define NB_W ((KWROWS * NDIM) / 256)          // 2048 blocks

__global__ void __launch_bounds__(256) prep_kernel(const float4* __restrict__ x,
                                                   const int* __restrict__ qw,
                                                   const float* __restrict__ sc) {
    if (blockIdx.x < NB_X) {
        int i = blockIdx.x * 256 + threadIdx.x;
        float4 a = x[2 * i];
        float4 b = x[2 * i + 1];
        __half2 h[4];
        h[0] = __floats2half2_rn(a.x, a.y);
        h[1] = __floats2half2_rn(a.z, a.w);
        h[2] = __floats2half2_rn(b.x, b.y);
        h[3] = __floats2half2_rn(b.z, b.w);
        reinterpret_cast<float4*>(g_X)[i] = *reinterpret_cast<float4*>(h);
    } else {
        int gid = (blockIdx.x - NB_X) * 256 + threadIdx.x;
        int kw = gid >> 12;
        int n  = gid & (NDIM - 1);
        uint32_t q = (uint32_t)qw[(size_t)kw * NDIM + n];
        float s = sc[(size_t)(kw >> 4) * NDIM + n];
        __half2 h[4];
#pragma unroll
        for (int j = 0; j < 4; ++j) {
            float lo = NF4_TBL[(q >> (8 * j)) & 15] * s;
            float hi = NF4_TBL[(q >> (8 * j + 4)) & 15] * s;
            h[j] = __floats2half2_rn(lo, hi);
        }
        *reinterpret_cast<float4*>(g_W + (size_t)n * KDIM + kw * 8) =
            *reinterpret_cast<float4*>(h);
    }
}

// ---------------------------------------------------------------------------
// GEMM: 128x256 CTA tile, 8 warps (2x4), warp tile 64x64, mbarrier ring,
// cross-iteration fragment pipelining.
// ---------------------------------------------------------------------------
struct Frag { uint32_t a[4][4]; uint32_t b[4][4]; };

__device__ __forceinline__ void load_frags(Frag& f, uint32_t stb, int ks,
                                           int a_row_base, uint32_t a_kh,
                                           int b_row_base, uint32_t b_kh) {
#pragma unroll
    for (int mt = 0; mt < 4; ++mt) {
        uint32_t bo = (uint32_t)((a_row_base + mt * 16) * 128 + ks * 32) + a_kh;
        LDSM4(f.a[mt], stb + SWZ(bo));
    }
#pragma unroll
    for (int nt = 0; nt < 4; ++nt) {
        uint32_t bo = (uint32_t)((b_row_base + nt * 16) * 128 + ks * 32) + b_kh;
        LDSM4(f.b[nt], stb + (uint32_t)A_BYTES + SWZ(bo));
    }
}

__device__ __forceinline__ void mma_step(float acc[4][8][4], const Frag& f) {
#pragma unroll
    for (int mt = 0; mt < 4; ++mt)
#pragma unroll
        for (int j = 0; j < 8; ++j)
            MMA16816(acc[mt][j], f.a[mt], f.b[j >> 1][(j & 1) * 2],
                     f.b[j >> 1][(j & 1) * 2 + 1]);
}

__global__ void __launch_bounds__(256, 1) gemm_f16(const float* __restrict__ bias,
                                                   float* __restrict__ out) {
    extern __shared__ char smem_raw[];
    const uint32_t sb = (smem_u32(smem_raw) + 1023) & ~1023u;  // mbarrier zone
    const uint32_t tb = sb + 1024;                              // tiles
    const int tid  = threadIdx.x;
    const int wid  = tid >> 5;
    const int lane = tid & 31;
    const int tile_n = blockIdx.x;
    const int tile_m = blockIdx.y;
    const int wm = wid >> 2;
    const int wn = wid & 3;

    if (tid == 0) {
#pragma unroll
        for (int s = 0; s < STAGES; ++s) {
            MBAR_INIT(sb + s * 16, 256);      // full[s]
            MBAR_INIT(sb + s * 16 + 8, 8);    // empty[s]
        }
    }
    __syncthreads();

    uint32_t a_sw[4], b_sw[8];
    int a_go[4], b_go[8];
#pragma unroll
    for (int j = 0; j < 4; ++j) {
        int c = tid + j * 256;
        int r = c >> 3, ci = c & 7;
        uint32_t bo = (uint32_t)(r * 128 + ci * 16);
        a_sw[j] = SWZ(bo);
        a_go[j] = r * KDIM + ci * 8;
    }
#pragma unroll
    for (int j = 0; j < 8; ++j) {
        int c = tid + j * 256;
        int r = c >> 3, ci = c & 7;
        uint32_t bo = (uint32_t)(r * 128 + ci * 16);
        b_sw[j] = (uint32_t)A_BYTES + SWZ(bo);
        b_go[j] = r * KDIM + ci * 8;
    }
    const __half* Ab = g_X + (size_t)tile_m * BM * KDIM;
    const __half* Bb = g_W + (size_t)tile_n * BN * KDIM;

    // prologue: fill all 4 stages
#pragma unroll
    for (int s = 0; s < STAGES; ++s) {
        uint32_t stb = tb + s * STAGE_BYTES;
        const __half* ap = Ab + s * BK;
        const __half* bp = Bb + s * BK;
#pragma unroll
        for (int j = 0; j < 4; ++j) CP_ASYNC16(stb + a_sw[j], ap + a_go[j]);
#pragma unroll
        for (int j = 0; j < 8; ++j) CP_ASYNC16(stb + b_sw[j], bp + b_go[j]);
        CP_ASYNC_MBAR_ARRIVE(sb + s * 16);
    }

    float acc[4][8][4];
#pragma unroll
    for (int i = 0; i < 4; ++i)
#pragma unroll
        for (int j = 0; j < 8; ++j)
#pragma unroll
            for (int k = 0; k < 4; ++k) acc[i][j][k] = 0.0f;

    const int a_row_base = wm * 64 + (lane & 15);
    const uint32_t a_kh  = (uint32_t)((lane >> 4) << 4);
    const int b_row_base = wn * 64 + ((lane >> 4) << 3) + (lane & 7);
    const uint32_t b_kh  = (uint32_t)(((lane >> 3) & 1) << 4);

    Frag f0, f1;

    // pre-loop: wait slot 0, load its ks=0 fragments
    MBAR_WAIT(sb + 0, 0);
    load_frags(f0, tb, 0, a_row_base, a_kh, b_row_base, b_kh);

#pragma unroll 1
    for (int it = 0; it < NITER; ++it) {
        const int slot = it & (STAGES - 1);
        const uint32_t ph = (uint32_t)((it >> 2) & 1);
        const uint32_t full_mb  = sb + slot * 16;
        const uint32_t empty_mb = full_mb + 8;
        const uint32_t stb = tb + slot * STAGE_BYTES;

        // f0 holds ks=0 of this iter on entry
        load_frags(f1, stb, 1, a_row_base, a_kh, b_row_base, b_kh);
        mma_step(acc, f0);                                          // ks=0
        load_frags(f0, stb, 2, a_row_base, a_kh, b_row_base, b_kh);
        mma_step(acc, f1);                                          // ks=1
        load_frags(f1, stb, 3, a_row_base, a_kh, b_row_base, b_kh);
        if (lane == 0) MBAR_ARRIVE(empty_mb);   // warp done reading slot
        mma_step(acc, f0);                                          // ks=2

        // hoist next iteration's full-wait + ks0 loads before the last mma
        if (it + 1 < NITER) {
            const int ns = (it + 1) & (STAGES - 1);
            const uint32_t nph = (uint32_t)(((it + 1) >> 2) & 1);
            MBAR_WAIT(sb + ns * 16, nph);
            load_frags(f0, tb + ns * STAGE_BYTES, 0,
                       a_row_base, a_kh, b_row_base, b_kh);
        }
        mma_step(acc, f1);                                          // ks=3

        // refill this slot for iteration it+STAGES (deadline 3 iters away)
        const int nx = it + STAGES;
        if (nx < NITER) {
            MBAR_WAIT(empty_mb, ph);
            const __half* ap = Ab + nx * BK;
            const __half* bp = Bb + nx * BK;
#pragma unroll
            for (int j = 0; j < 4; ++j) CP_ASYNC16(stb + a_sw[j], ap + a_go[j]);
#pragma unroll
            for (int j = 0; j < 8; ++j) CP_ASYNC16(stb + b_sw[j], bp + b_go[j]);
            CP_ASYNC_MBAR_ARRIVE(full_mb);
        }
    }

    // epilogue: bias + store
    const int m0 = tile_m * BM + wm * 64 + (lane >> 2);
    const int n0 = tile_n * BN + wn * 64 + 2 * (lane & 3);
#pragma unroll
    for (int j = 0; j < 8; ++j) {
        const int n = n0 + j * 8;
        const float2 bv = *reinterpret_cast<const float2*>(bias + n);
#pragma unroll
        for (int mt = 0; mt < 4; ++mt) {
            const int m = m0 + mt * 16;
            float2 v0, v1;
            v0.x = acc[mt][j][0] + bv.x;
            v0.y = acc[mt][j][1] + bv.y;
            v1.x = acc[mt][j][2] + bv.x;
            v1.y = acc[mt][j][3] + bv.y;
            *reinterpret_cast<float2*>(out + (size_t)m * NDIM + n) = v0;
            *reinterpret_cast<float2*>(out + (size_t)(m + 8) * NDIM + n) = v1;
        }
    }
}

// ---------------------------------------------------------------------------
extern "C" void kernel_launch(void* const* d_in, const int* in_sizes, int n_in,
                              void* d_out, int out_size) {
    const float* x       = (const float*)d_in[0];
    const float* scales  = (const float*)d_in[1];
    const float* bias    = (const float*)d_in[2];
    const int*   qweight = (const int*)d_in[3];
    float* out = (float*)d_out;

    cudaFuncSetAttribute(gemm_f16, cudaFuncAttributeMaxDynamicSharedMemorySize,
                         SMEM_TOTAL);

    prep_kernel<<<NB_X + NB_W, 256>>>((const float4*)x, qweight, scales);
    gemm_f16<<<dim3(NDIM / BN, MDIM / BM), 256, SMEM_TOTAL>>>(bias, out);
}

// round 15
// speedup vs baseline: 1.2263x; 1.0135x over previous
#include <cuda_runtime.h>
#include <cuda_fp16.h>
#include <cstdint>

// ---------------------------------------------------------------------------
// out[8192,4096] = x[8192,4096] @ dequantNF4(qweight,scales)[4096,4096] + bias
// sm_100 PTX target => no tcgen05. mma.sync.m16n8k16 f16 (rt~8cyc/SMSP).
// R15 (= R14 resubmitted; R14 hit broker flake, cf. R4->R5 and R6->R8):
// persistent CTAs (grid=148) with cross-tile continuous mbarrier ring:
// refills stream the NEXT tile's k-chunks during the current tile's last
// iterations, so prologue exposure and wave transitions vanish and next-tile
// fills overlap the epilogue.
// ---------------------------------------------------------------------------
#define MDIM 8192
#define NDIM 4096
#define KDIM 4096
#define KWROWS (KDIM / 8)

#define BM 128
#define BN 256
#define BK 64                          // fp16 elems / K-chunk: 128-byte rows
#define STAGES 4
#define NITER (KDIM / BK)              // 64
#define A_BYTES (BM * BK * 2)          // 16384
#define B_BYTES (BN * BK * 2)          // 32768
#define STAGE_BYTES (A_BYTES + B_BYTES)            // 49152
#define SMEM_TOTAL (1024 + 1024 + STAGES * STAGE_BYTES)   // 198656

#define NTILES ((MDIM / BM) * (NDIM / BN))   // 64 * 16 = 1024
#define GRID 148
#define TN_MASK 15                           // NDIM/BN - 1
#define TM_SHIFT 4                           // log2(NDIM/BN)

#define SWZ(bo) ((bo) ^ (((bo) >> 3) & 0x70))

__device__ __align__(16) __half g_X[(size_t)MDIM * KDIM];   // [M,K]
__device__ __align__(16) __half g_W[(size_t)NDIM * KDIM];   // [N,K] K-major

__device__ const float NF4_TBL[16] = {
    -1.0f, -0.6961928009986877f, -0.5250730514526367f, -0.39491748809814453f,
    -0.28444138169288635f, -0.18477343022823334f, -0.09105003625154495f, 0.0f,
    0.07958029955625534f, 0.16093020141124725f, 0.24611230194568634f,
    0.33791524171829224f, 0.44070982933044434f, 0.5626170039176941f,
    0.7229568362236023f, 1.0f};

__device__ __forceinline__ uint32_t smem_u32(const void* p) {
    uint32_t a;
    asm("{ .reg .u64 t; cvta.to.shared.u64 t, %1; cvt.u32.u64 %0, t; }"
        : "=r"(a) : "l"(p));
    return a;
}

#define CP_ASYNC16(smem, gptr) \
    asm volatile("cp.async.cg.shared.global [%0], [%1], 16;" \
                 :: "r"(smem), "l"(gptr) : "memory")

#define CP_ASYNC_MBAR_ARRIVE(mbar) \
    asm volatile("cp.async.mbarrier.arrive.noinc.shared.b64 [%0];" \
                 :: "r"(mbar) : "memory")

#define MBAR_INIT(addr, cnt) \
    asm volatile("mbarrier.init.shared.b64 [%0], %1;" :: "r"(addr), "r"((uint32_t)(cnt)) : "memory")

#define MBAR_ARRIVE(addr) \
    asm volatile("mbarrier.arrive.shared.b64 _, [%0];" :: "r"(addr) : "memory")

#define MBAR_WAIT(addr, par) do {                                              \
    uint32_t _m = (addr); uint32_t _p = (par); uint32_t _d;                    \
    asm volatile(                                                              \
        "{\n\t.reg .pred p;\n\t"                                               \
        "mbarrier.try_wait.parity.shared.b64 p, [%1], %2;\n\t"                 \
        "selp.b32 %0, 1, 0, p;\n\t}"                                           \
        : "=r"(_d) : "r"(_m), "r"(_p) : "memory");                             \
    if (!_d) {                                                                 \
        asm volatile(                                                          \
            "{\n\t.reg .pred P1;\n\t"                                          \
            "WL_%=:\n\t"                                                       \
            "mbarrier.try_wait.parity.shared.b64 P1, [%0], %1;\n\t"            \
            "@P1 bra.uni WD_%=;\n\t"                                           \
            "bra.uni WL_%=;\n\t"                                               \
            "WD_%=:\n\t}"                                                      \
            :: "r"(_m), "r"(_p) : "memory");                                   \
    }                                                                          \
} while (0)

#define LDSM4(r, addr)                                                         \
    asm volatile("ldmatrix.sync.aligned.m8n8.x4.shared.b16 {%0,%1,%2,%3}, [%4];" \
                 : "=r"((r)[0]), "=r"((r)[1]), "=r"((r)[2]), "=r"((r)[3])      \
                 : "r"(addr))

#define MMA16816(c, a, b0, b1)                                                 \
    asm volatile("mma.sync.aligned.m16n8k16.row.col.f32.f16.f16.f32 "          \
                 "{%0,%1,%2,%3}, {%4,%5,%6,%7}, {%8,%9}, {%0,%1,%2,%3};"       \
                 : "+f"((c)[0]), "+f"((c)[1]), "+f"((c)[2]), "+f"((c)[3])      \
                 : "r"((a)[0]), "r"((a)[1]), "r"((a)[2]), "r"((a)[3]),         \
                   "r"(b0), "r"(b1))

// ---------------------------------------------------------------------------
// Fused prelude
// ---------------------------------------------------------------------------
#define NB_X ((MDIM * KDIM / 8) / 256)        // 16384 blocks
#define NB_W ((KWROWS * NDIM) / 256)          // 2048 blocks

__global__ void __launch_bounds__(256) prep_kernel(const float4* __restrict__ x,
                                                   const int* __restrict__ qw,
                                                   const float* __restrict__ sc) {
    if (blockIdx.x < NB_X) {
        int i = blockIdx.x * 256 + threadIdx.x;
        float4 a = x[2 * i];
        float4 b = x[2 * i + 1];
        __half2 h[4];
        h[0] = __floats2half2_rn(a.x, a.y);
        h[1] = __floats2half2_rn(a.z, a.w);
        h[2] = __floats2half2_rn(b.x, b.y);
        h[3] = __floats2half2_rn(b.z, b.w);
        reinterpret_cast<float4*>(g_X)[i] = *reinterpret_cast<float4*>(h);
    } else {
        int gid = (blockIdx.x - NB_X) * 256 + threadIdx.x;
        int kw = gid >> 12;
        int n  = gid & (NDIM - 1);
        uint32_t q = (uint32_t)qw[(size_t)kw * NDIM + n];
        float s = sc[(size_t)(kw >> 4) * NDIM + n];
        __half2 h[4];
#pragma unroll
        for (int j = 0; j < 4; ++j) {
            float lo = NF4_TBL[(q >> (8 * j)) & 15] * s;
            float hi = NF4_TBL[(q >> (8 * j + 4)) & 15] * s;
            h[j] = __floats2half2_rn(lo, hi);
        }
        *reinterpret_cast<float4*>(g_W + (size_t)n * KDIM + kw * 8) =
            *reinterpret_cast<float4*>(h);
    }
}

// ---------------------------------------------------------------------------
// GEMM: persistent 128x256 tiles, 8 warps (2x4), warp tile 64x64,
// mbarrier ring continuous across tiles.
// ---------------------------------------------------------------------------
struct Frag { uint32_t a[4][4]; uint32_t b[4][4]; };

__device__ __forceinline__ void load_frags(Frag& f, uint32_t stb, int ks,
                                           int a_row_base, uint32_t a_kh,
                                           int b_row_base, uint32_t b_kh) {
#pragma unroll
    for (int mt = 0; mt < 4; ++mt) {
        uint32_t bo = (uint32_t)((a_row_base + mt * 16) * 128 + ks * 32) + a_kh;
        LDSM4(f.a[mt], stb + SWZ(bo));
    }
#pragma unroll
    for (int nt = 0; nt < 4; ++nt) {
        uint32_t bo = (uint32_t)((b_row_base + nt * 16) * 128 + ks * 32) + b_kh;
        LDSM4(f.b[nt], stb + (uint32_t)A_BYTES + SWZ(bo));
    }
}

__device__ __forceinline__ void mma_step(float acc[4][8][4], const Frag& f) {
#pragma unroll
    for (int mt = 0; mt < 4; ++mt)
#pragma unroll
        for (int j = 0; j < 8; ++j)
            MMA16816(acc[mt][j], f.a[mt], f.b[j >> 1][(j & 1) * 2],
                     f.b[j >> 1][(j & 1) * 2 + 1]);
}

__global__ void __launch_bounds__(256, 1) gemm_f16(const float* __restrict__ bias,
                                                   float* __restrict__ out) {
    extern __shared__ char smem_raw[];
    const uint32_t sb = (smem_u32(smem_raw) + 1023) & ~1023u;  // mbarrier zone
    const uint32_t tb = sb + 1024;                              // tiles
    const int tid  = threadIdx.x;
    const int wid  = tid >> 5;
    const int lane = tid & 31;
    const int wm = wid >> 2;
    const int wn = wid & 3;

    if (tid == 0) {
#pragma unroll
        for (int s = 0; s < STAGES; ++s) {
            MBAR_INIT(sb + s * 16, 256);      // full[s]
            MBAR_INIT(sb + s * 16 + 8, 8);    // empty[s]
        }
    }
    __syncthreads();

    uint32_t a_sw[4], b_sw[8];
    int a_go[4], b_go[8];
#pragma unroll
    for (int j = 0; j < 4; ++j) {
        int c = tid + j * 256;
        int r = c >> 3, ci = c & 7;
        uint32_t bo = (uint32_t)(r * 128 + ci * 16);
        a_sw[j] = SWZ(bo);
        a_go[j] = r * KDIM + ci * 8;
    }
#pragma unroll
    for (int j = 0; j < 8; ++j) {
        int c = tid + j * 256;
        int r = c >> 3, ci = c & 7;
        uint32_t bo = (uint32_t)(r * 128 + ci * 16);
        b_sw[j] = (uint32_t)A_BYTES + SWZ(bo);
        b_go[j] = r * KDIM + ci * 8;
    }

    int t = blockIdx.x;                       // current tile id
    const __half* Ab = g_X + (size_t)(t >> TM_SHIFT) * BM * KDIM;
    const __half* Bb = g_W + (size_t)(t & TN_MASK) * BN * KDIM;

    // prologue: fill all 4 stages from first tile
#pragma unroll
    for (int s = 0; s < STAGES; ++s) {
        uint32_t stb = tb + s * STAGE_BYTES;
        const __half* ap = Ab + s * BK;
        const __half* bp = Bb + s * BK;
#pragma unroll
        for (int j = 0; j < 4; ++j) CP_ASYNC16(stb + a_sw[j], ap + a_go[j]);
#pragma unroll
        for (int j = 0; j < 8; ++j) CP_ASYNC16(stb + b_sw[j], bp + b_go[j]);
        CP_ASYNC_MBAR_ARRIVE(sb + s * 16);
    }

    float acc[4][8][4];
#pragma unroll
    for (int i = 0; i < 4; ++i)
#pragma unroll
        for (int j = 0; j < 8; ++j)
#pragma unroll
            for (int k = 0; k < 4; ++k) acc[i][j][k] = 0.0f;

    const int a_row_base = wm * 64 + (lane & 15);
    const uint32_t a_kh  = (uint32_t)((lane >> 4) << 4);
    const int b_row_base = wn * 64 + ((lane >> 4) << 3) + (lane & 7);
    const uint32_t b_kh  = (uint32_t)(((lane >> 3) & 1) << 4);

    Frag f0, f1;

    MBAR_WAIT(sb + 0, 0);
    load_frags(f0, tb, 0, a_row_base, a_kh, b_row_base, b_kh);

#pragma unroll 1
    for (;;) {
        const int tnext = t + GRID;
        const bool has_next = tnext < NTILES;

#pragma unroll 1
        for (int it = 0; it < NITER; ++it) {
            const int slot = it & (STAGES - 1);
            const uint32_t ph = (uint32_t)((it >> 2) & 1);
            const uint32_t full_mb  = sb + slot * 16;
            const uint32_t empty_mb = full_mb + 8;
            const uint32_t stb = tb + slot * STAGE_BYTES;

            // f0 holds ks=0 of this iter on entry
            load_frags(f1, stb, 1, a_row_base, a_kh, b_row_base, b_kh);
            mma_step(acc, f0);                                          // ks=0
            load_frags(f0, stb, 2, a_row_base, a_kh, b_row_base, b_kh);
            mma_step(acc, f1);                                          // ks=1
            load_frags(f1, stb, 3, a_row_base, a_kh, b_row_base, b_kh);
            if (lane == 0) MBAR_ARRIVE(empty_mb);
            mma_step(acc, f0);                                          // ks=2

            // hoist next-iteration full-wait + ks0 loads (crosses tile end)
            if (it + 1 < NITER || has_next) {
                const int ni = it + 1;
                const int ns = ni & (STAGES - 1);
                const uint32_t nph = (uint32_t)((ni >> 2) & 1);  // ni=64 -> 0
                MBAR_WAIT(sb + ns * 16, nph);
                load_frags(f0, tb + ns * STAGE_BYTES, 0,
                           a_row_base, a_kh, b_row_base, b_kh);
            }
            mma_step(acc, f1);                                          // ks=3

            // refill this slot: current tile k=it+4, or next tile k=it-60
            const int nx = it + STAGES;
            const __half *ap, *bp;
            bool do_ref = false;
            if (nx < NITER) {
                ap = Ab + nx * BK;
                bp = Bb + nx * BK;
                do_ref = true;
            } else if (has_next) {
                ap = g_X + (size_t)(tnext >> TM_SHIFT) * BM * KDIM + (nx - NITER) * BK;
                bp = g_W + (size_t)(tnext & TN_MASK) * BN * KDIM + (nx - NITER) * BK;
                do_ref = true;
            }
            if (do_ref) {
                MBAR_WAIT(empty_mb, ph);
#pragma unroll
                for (int j = 0; j < 4; ++j) CP_ASYNC16(stb + a_sw[j], ap + a_go[j]);
#pragma unroll
                for (int j = 0; j < 8; ++j) CP_ASYNC16(stb + b_sw[j], bp + b_go[j]);
                CP_ASYNC_MBAR_ARRIVE(full_mb);
            }
        }

        // epilogue for tile t (overlaps with next tile's in-flight fills)
        {
            const int m0 = (t >> TM_SHIFT) * BM + wm * 64 + (lane >> 2);
            const int n0 = (t & TN_MASK) * BN + wn * 64 + 2 * (lane & 3);
#pragma unroll
            for (int j = 0; j < 8; ++j) {
                const int n = n0 + j * 8;
                const float2 bv = *reinterpret_cast<const float2*>(bias + n);
#pragma unroll
                for (int mt = 0; mt < 4; ++mt) {
                    const int m = m0 + mt * 16;
                    float2 v0, v1;
                    v0.x = acc[mt][j][0] + bv.x;
                    v0.y = acc[mt][j][1] + bv.y;
                    v1.x = acc[mt][j][2] + bv.x;
                    v1.y = acc[mt][j][3] + bv.y;
                    *reinterpret_cast<float2*>(out + (size_t)m * NDIM + n) = v0;
                    *reinterpret_cast<float2*>(out + (size_t)(m + 8) * NDIM + n) = v1;
                }
            }
        }
        if (!has_next) break;

#pragma unroll
        for (int i = 0; i < 4; ++i)
#pragma unroll
            for (int j = 0; j < 8; ++j)
#pragma unroll
                for (int k = 0; k < 4; ++k) acc[i][j][k] = 0.0f;

        t = tnext;
        Ab = g_X + (size_t)(t >> TM_SHIFT) * BM * KDIM;
        Bb = g_W + (size_t)(t & TN_MASK) * BN * KDIM;
    }
}

// ---------------------------------------------------------------------------
extern "C" void kernel_launch(void* const* d_in, const int* in_sizes, int n_in,
                              void* d_out, int out_size) {
    const float* x       = (const float*)d_in[0];
    const float* scales  = (const float*)d_in[1];
    const float* bias    = (const float*)d_in[2];
    const int*   qweight = (const int*)d_in[3];
    float* out = (float*)d_out;

    cudaFuncSetAttribute(gemm_f16, cudaFuncAttributeMaxDynamicSharedMemorySize,
                         SMEM_TOTAL);

    prep_kernel<<<NB_X + NB_W, 256>>>((const float4*)x, qweight, scales);
    gemm_f16<<<GRID, 256, SMEM_TOTAL>>>(bias, out);
}